// round 10
// baseline (speedup 1.0000x reference)
#include <cuda_runtime.h>
#include <cuda_bf16.h>

// 3x3 PCF shadow visibility, 2 px/thread, persistent grid-stride tiles.
// vis = (1/9) * sum sigmoid((zbuf[b, clamp(y+ii), clamp(x+jj)] - (z - 0.008)) * 1000)

#define TILE_PX 512   // 256 threads * 2 px

__device__ __forceinline__ float ex2f(float x) {
    float y; asm("ex2.approx.f32 %0, %1;" : "=f"(y) : "f"(x)); return y;
}
__device__ __forceinline__ float rcpf(float x) {
    float y; asm("rcp.approx.f32 %0, %1;" : "=f"(y) : "f"(x)); return y;
}
__device__ __forceinline__ float quad_sum(float p0, float p1, float p2, float p3) {
    float a = p0 * p1, b = p2 * p3;
    return ((p0 + p1) * b + (p2 + p3) * a) * rcpf(a * b);
}
__device__ __forceinline__ float pval(float v, float C, float K) {
    float u = fmaf(-v, K, C);
    u = fminf(u, 30.0f);
    return 1.0f + ex2f(u);
}

__global__ __launch_bounds__(256) void shadow_pcf_pers_kernel(
    const float* __restrict__ zbuf,       // [N, S, S]
    const float* __restrict__ depth,      // [N, H, W, K]
    const int*   __restrict__ xy,         // [N, H, W, K, 2]
    const int*   __restrict__ image_size, // scalar S (device)
    float*       __restrict__ out,        // [N, H, W, K]
    int total,                            // N*H*W*K
    int zbuf_total)                       // N*S*S
{
    __shared__ int sm_S, sm_hwk, sm_shift;   // shift >= 0 iff HWK is pow2
    __shared__ unsigned sm_SS;

    if (threadIdx.x == 0) {
        int S = *image_size;
        unsigned SS = (unsigned)S * (unsigned)S;
        int N   = (int)((unsigned)zbuf_total / SS);
        if (N < 1) N = 1;
        int HWK = total / N;
        if (HWK < 1) HWK = 1;
        int shift = -1;
        if ((HWK & (HWK - 1)) == 0) shift = __ffs(HWK) - 1;
        sm_S = S; sm_SS = SS; sm_hwk = HWK; sm_shift = shift;
    }
    __syncthreads();     // once per block; smem is read-only afterwards

    const int S       = sm_S;
    const unsigned SS = sm_SS;
    const int HWK     = sm_hwk;
    const int shift   = sm_shift;
    const float Kc = 1000.0f * 1.4426950408889634f;
    const bool fastS = ((S & 3) == 0);

    const int ntiles = (total + TILE_PX - 1) / TILE_PX;

    for (int tile = blockIdx.x; tile < ntiles; tile += gridDim.x) {
        const int base = tile * TILE_PX;
        const int idx0 = base + 2 * threadIdx.x;
        if (idx0 >= total) continue;
        const bool has2 = (idx0 + 1) < total;

        int xs[2], ys[2];
        float C_[2];
        if (has2) {
            int4   cc = __ldg((const int4*)(xy + 2 * idx0));   // x0,y0,x1,y1
            float2 dd = __ldg((const float2*)(depth + idx0));
            xs[0] = cc.x; ys[0] = cc.y; xs[1] = cc.z; ys[1] = cc.w;
            C_[0] = (dd.x - 0.008f) * Kc;
            C_[1] = (dd.y - 0.008f) * Kc;
        } else {
            int2 cc = __ldg((const int2*)(xy + 2 * idx0));
            xs[0] = cc.x; ys[0] = cc.y; xs[1] = 0; ys[1] = 0;
            C_[0] = (__ldg(depth + idx0) - 0.008f) * Kc;
            C_[1] = 0.0f;
        }

        // batch index per pixel: pow2 shift (common) or udiv (rare shapes)
        int b_[2];
        if (shift >= 0) {
            b_[0] = idx0 >> shift;
            b_[1] = (idx0 + 1) >> shift;
        } else {
            b_[0] = idx0 / HWK;
            b_[1] = (idx0 + 1) / HWK;
        }

        float acc[2] = {0.0f, 0.0f};

        if (fastS && has2) {
            // ---- fast path: rows 16B-aligned ----
            unsigned off[2][3];
            bool d2_[2], d1_[2], lo_[2], hi_[2], nq_[2];

#pragma unroll
            for (int p = 0; p < 2; ++p) {
                const int x = xs[p], y = ys[p];
                const int ym = max(y - 1, 0);
                const int yp = min(y + 1, S - 1);
                const int xi = min(max(x, 1), S - 2);
                const int c0 = xi - 1;
                const int e16 = c0 & ~3;
                const int d   = c0 - e16;          // 0..3
                nq_[p] = (d >= 2);
                d2_[p] = (d & 2) != 0;
                d1_[p] = (d & 1) != 0;
                lo_[p] = (x < 1);
                hi_[p] = (x > S - 2);
                unsigned bb = (unsigned)b_[p] * SS + (unsigned)e16;
                off[p][0] = bb + (unsigned)ym * (unsigned)S;
                off[p][1] = bb + (unsigned)y  * (unsigned)S;
                off[p][2] = bb + (unsigned)yp * (unsigned)S;
            }

            // Issue all gathers before any consumption (max MLP).
            float4 P[2][3];
            float2 Q[2][3];
#pragma unroll
            for (int p = 0; p < 2; ++p)
#pragma unroll
                for (int r = 0; r < 3; ++r)
                    P[p][r] = __ldg((const float4*)(zbuf + off[p][r]));
#pragma unroll
            for (int p = 0; p < 2; ++p)
#pragma unroll
                for (int r = 0; r < 3; ++r) {
                    Q[p][r] = make_float2(0.0f, 0.0f);
                    if (nq_[p]) Q[p][r] = __ldg((const float2*)(zbuf + off[p][r] + 4));
                }

#pragma unroll
            for (int p = 0; p < 2; ++p) {
                const bool d2 = d2_[p], d1 = d1_[p], lo = lo_[p], hi = hi_[p];
                const float C = C_[p];
                float pv[9];
#pragma unroll
                for (int r = 0; r < 3; ++r) {
                    float g0 = d2 ? P[p][r].z : P[p][r].x;
                    float g1 = d2 ? P[p][r].w : P[p][r].y;
                    float g2 = d2 ? Q[p][r].x : P[p][r].z;
                    float g3 = d2 ? Q[p][r].y : P[p][r].w;
                    float t0 = d1 ? g1 : g0;
                    float t1 = d1 ? g2 : g1;
                    float t2 = d1 ? g3 : g2;
                    float vl = hi ? t1 : t0;
                    float vm = lo ? t0 : (hi ? t2 : t1);
                    float vr = lo ? t1 : t2;
                    pv[3 * r + 0] = pval(vl, C, Kc);
                    pv[3 * r + 1] = pval(vm, C, Kc);
                    pv[3 * r + 2] = pval(vr, C, Kc);
                }
                acc[p] = quad_sum(pv[0], pv[1], pv[2], pv[3])
                       + quad_sum(pv[4], pv[5], pv[6], pv[7])
                       + rcpf(pv[8]);
            }

            float2 o = make_float2(acc[0] * (1.0f / 9.0f), acc[1] * (1.0f / 9.0f));
            *(float2*)(out + idx0) = o;
        } else {
            // ---- generic path: scalar gathers ----
            for (int p = 0; p < 2; ++p) {
                const int idx = idx0 + p;
                if (p == 1 && !has2) break;
                const int x = xs[p], y = ys[p];
                const int xm = max(x - 1, 0), xp = min(x + 1, S - 1);
                const int ym = max(y - 1, 0), yp = min(y + 1, S - 1);
                const float* zb = zbuf + (size_t)b_[p] * (size_t)SS;
                const float C = C_[p];
                float a = 0.0f;
                int yy[3] = {ym, y, yp};
                for (int r = 0; r < 3; ++r) {
                    const float* rr = zb + (size_t)(unsigned)yy[r] * (unsigned)S;
                    a += rcpf(pval(__ldg(rr + xm), C, Kc));
                    a += rcpf(pval(__ldg(rr + x ), C, Kc));
                    a += rcpf(pval(__ldg(rr + xp), C, Kc));
                }
                out[idx] = a * (1.0f / 9.0f);
            }
        }
    }
}

extern "C" void kernel_launch(void* const* d_in, const int* in_sizes, int n_in,
                              void* d_out, int out_size) {
    const float* zbuf   = (const float*)d_in[0];
    const float* depth  = (const float*)d_in[1];
    const int*   xy     = (const int*)  d_in[2];
    const int*   imsz   = (const int*)  d_in[3];
    float*       out    = (float*)d_out;

    const int total      = in_sizes[1];
    const int zbuf_total = in_sizes[0];

    const int ntiles = (total + TILE_PX - 1) / TILE_PX;
    int blocks = 148 * 8;                 // persistent-ish; grid-stride handles rest
    if (blocks > ntiles) blocks = ntiles;
    if (blocks < 1) blocks = 1;
    shadow_pcf_pers_kernel<<<blocks, 256>>>(zbuf, depth, xy, imsz, out,
                                            total, zbuf_total);
}

// round 11
// speedup vs baseline: 1.1634x; 1.1634x over previous
#include <cuda_runtime.h>
#include <cuda_bf16.h>

// 3x3 PCF shadow visibility, 2 pixels per thread (R4 datapath, barrier-free front end):
// vis = (1/9) * sum sigmoid((zbuf[b, clamp(y+ii), clamp(x+jj)] - (z - 0.008)) * 1000)

__device__ __forceinline__ float ex2f(float x) {
    float y; asm("ex2.approx.f32 %0, %1;" : "=f"(y) : "f"(x)); return y;
}
__device__ __forceinline__ float rcpf(float x) {
    float y; asm("rcp.approx.f32 %0, %1;" : "=f"(y) : "f"(x)); return y;
}
__device__ __forceinline__ float quad_sum(float p0, float p1, float p2, float p3) {
    float a = p0 * p1, b = p2 * p3;
    return ((p0 + p1) * b + (p2 + p3) * a) * rcpf(a * b);
}
__device__ __forceinline__ float pval(float v, float C, float K) {
    float u = fmaf(-v, K, C);
    u = fminf(u, 30.0f);
    return 1.0f + ex2f(u);
}

__global__ __launch_bounds__(256) void shadow_pcf2_kernel(
    const float* __restrict__ zbuf,       // [N, S, S]
    const float* __restrict__ depth,      // [N, H, W, K]
    const int*   __restrict__ xy,         // [N, H, W, K, 2]
    const int*   __restrict__ image_size, // scalar S (device)
    float*       __restrict__ out,        // [N, H, W, K]
    int total,                            // N*H*W*K
    int zbuf_total)                       // N*S*S
{
    const int i    = blockIdx.x * blockDim.x + threadIdx.x;
    const int idx0 = 2 * i;
    if (idx0 >= total) return;

    // Uniform per-thread setup (no smem, no __syncthreads): S is a warp-broadcast
    // L1-hit load; the two udivs are uniform and off the gather critical path.
    const int S = __ldg(image_size);
    const unsigned SS = (unsigned)S * (unsigned)S;
    int N = (int)((unsigned)zbuf_total / SS);
    if (N < 1) N = 1;
    int HWK = total / N;
    if (HWK < 1) HWK = 1;

    const bool has2 = (idx0 + 1) < total;
    const float Kc = 1000.0f * 1.4426950408889634f;

    // batch index per pixel: pow2 shift (common case) or udiv
    int b_[2];
    if ((HWK & (HWK - 1)) == 0) {
        const int sh = __ffs(HWK) - 1;
        b_[0] = idx0 >> sh;
        b_[1] = (idx0 + 1) >> sh;
    } else {
        b_[0] = idx0 / HWK;
        b_[1] = (idx0 + 1) / HWK;
    }

    int xs[2], ys[2];
    float C_[2];
    if (has2) {
        int4   cc = __ldg((const int4*)(xy + 2 * idx0));     // x0,y0,x1,y1
        float2 dd = __ldg((const float2*)(depth + idx0));
        xs[0] = cc.x; ys[0] = cc.y; xs[1] = cc.z; ys[1] = cc.w;
        C_[0] = (dd.x - 0.008f) * Kc;
        C_[1] = (dd.y - 0.008f) * Kc;
    } else {
        int2 cc = __ldg((const int2*)(xy + 2 * idx0));
        xs[0] = cc.x; ys[0] = cc.y; xs[1] = 0; ys[1] = 0;
        C_[0] = (__ldg(depth + idx0) - 0.008f) * Kc;
        C_[1] = 0.0f;
    }

    float acc[2] = {0.0f, 0.0f};

    if (((S & 3) == 0) && has2) {
        // ---- fast path: rows 16B-aligned ----
        const float* rows[2][3];
        bool d2_[2], d1_[2], lo_[2], hi_[2], nq_[2];

#pragma unroll
        for (int p = 0; p < 2; ++p) {
            const int x = xs[p], y = ys[p];
            const int ym = max(y - 1, 0);
            const int yp = min(y + 1, S - 1);
            const int xi = min(max(x, 1), S - 2);
            const int c0 = xi - 1;
            const int e16 = c0 & ~3;
            const int d   = c0 - e16;          // 0..3
            nq_[p] = (d >= 2);
            d2_[p] = (d & 2) != 0;
            d1_[p] = (d & 1) != 0;
            lo_[p] = (x < 1);
            hi_[p] = (x > S - 2);
            const float* zb = zbuf + (size_t)b_[p] * (size_t)SS;
            rows[p][0] = zb + (size_t)(unsigned)ym * (unsigned)S + e16;
            rows[p][1] = zb + (size_t)(unsigned)y  * (unsigned)S + e16;
            rows[p][2] = zb + (size_t)(unsigned)yp * (unsigned)S + e16;
        }

        // Issue all gathers before any consumption (max MLP).
        float4 P[2][3];
        float2 Q[2][3];
#pragma unroll
        for (int p = 0; p < 2; ++p)
#pragma unroll
            for (int r = 0; r < 3; ++r)
                P[p][r] = __ldg((const float4*)rows[p][r]);
#pragma unroll
        for (int p = 0; p < 2; ++p)
#pragma unroll
            for (int r = 0; r < 3; ++r) {
                Q[p][r] = make_float2(0.0f, 0.0f);
                if (nq_[p]) Q[p][r] = __ldg((const float2*)(rows[p][r] + 4));
            }

#pragma unroll
        for (int p = 0; p < 2; ++p) {
            const bool d2 = d2_[p], d1 = d1_[p], lo = lo_[p], hi = hi_[p];
            const float C = C_[p];
            float pv[9];
#pragma unroll
            for (int r = 0; r < 3; ++r) {
                float g0 = d2 ? P[p][r].z : P[p][r].x;
                float g1 = d2 ? P[p][r].w : P[p][r].y;
                float g2 = d2 ? Q[p][r].x : P[p][r].z;
                float g3 = d2 ? Q[p][r].y : P[p][r].w;
                float t0 = d1 ? g1 : g0;
                float t1 = d1 ? g2 : g1;
                float t2 = d1 ? g3 : g2;
                float vl = hi ? t1 : t0;
                float vm = lo ? t0 : (hi ? t2 : t1);
                float vr = lo ? t1 : t2;
                pv[3 * r + 0] = pval(vl, C, Kc);
                pv[3 * r + 1] = pval(vm, C, Kc);
                pv[3 * r + 2] = pval(vr, C, Kc);
            }
            acc[p] = quad_sum(pv[0], pv[1], pv[2], pv[3])
                   + quad_sum(pv[4], pv[5], pv[6], pv[7])
                   + rcpf(pv[8]);
        }

        float2 o = make_float2(acc[0] * (1.0f / 9.0f), acc[1] * (1.0f / 9.0f));
        *(float2*)(out + idx0) = o;
    } else {
        // ---- generic path: scalar gathers, rolled ----
        for (int p = 0; p < 2; ++p) {
            const int idx = idx0 + p;
            if (p == 1 && !has2) break;
            const int x = xs[p], y = ys[p];
            const int xm = max(x - 1, 0), xp = min(x + 1, S - 1);
            const int ym = max(y - 1, 0), yp = min(y + 1, S - 1);
            const float* zb = zbuf + (size_t)b_[p] * (size_t)SS;
            const float C = C_[p];
            float a = 0.0f;
            int yy[3] = {ym, y, yp};
            for (int r = 0; r < 3; ++r) {
                const float* rr = zb + (size_t)(unsigned)yy[r] * (unsigned)S;
                a += rcpf(pval(__ldg(rr + xm), C, Kc));
                a += rcpf(pval(__ldg(rr + x ), C, Kc));
                a += rcpf(pval(__ldg(rr + xp), C, Kc));
            }
            out[idx] = a * (1.0f / 9.0f);
        }
    }
}

extern "C" void kernel_launch(void* const* d_in, const int* in_sizes, int n_in,
                              void* d_out, int out_size) {
    const float* zbuf   = (const float*)d_in[0];
    const float* depth  = (const float*)d_in[1];
    const int*   xy     = (const int*)  d_in[2];
    const int*   imsz   = (const int*)  d_in[3];
    float*       out    = (float*)d_out;

    const int total      = in_sizes[1];
    const int zbuf_total = in_sizes[0];

    const int threads = 256;
    const int pairs   = (total + 1) / 2;
    const int blocks  = (pairs + threads - 1) / threads;
    shadow_pcf2_kernel<<<blocks, threads>>>(zbuf, depth, xy, imsz, out,
                                            total, zbuf_total);
}

// round 12
// speedup vs baseline: 1.1741x; 1.0092x over previous
#include <cuda_runtime.h>
#include <cuda_bf16.h>

// 3x3 PCF shadow visibility, 2 pixels per thread, 128-thread blocks:
// vis = (1/9) * sum sigmoid((zbuf[b, clamp(y+ii), clamp(x+jj)] - (z - 0.008)) * 1000)

__device__ __forceinline__ float ex2f(float x) {
    float y; asm("ex2.approx.f32 %0, %1;" : "=f"(y) : "f"(x)); return y;
}
__device__ __forceinline__ float rcpf(float x) {
    float y; asm("rcp.approx.f32 %0, %1;" : "=f"(y) : "f"(x)); return y;
}
__device__ __forceinline__ float quad_sum(float p0, float p1, float p2, float p3) {
    float a = p0 * p1, b = p2 * p3;
    return ((p0 + p1) * b + (p2 + p3) * a) * rcpf(a * b);
}
__device__ __forceinline__ float pval(float v, float C, float K) {
    float u = fmaf(-v, K, C);
    u = fminf(u, 30.0f);
    return 1.0f + ex2f(u);
}

__global__ __launch_bounds__(128) void shadow_pcf2_kernel(
    const float* __restrict__ zbuf,       // [N, S, S]
    const float* __restrict__ depth,      // [N, H, W, K]
    const int*   __restrict__ xy,         // [N, H, W, K, 2]
    const int*   __restrict__ image_size, // scalar S (device)
    float*       __restrict__ out,        // [N, H, W, K]
    int total,                            // N*H*W*K
    int zbuf_total)                       // N*S*S
{
    const int i    = blockIdx.x * blockDim.x + threadIdx.x;
    const int idx0 = 2 * i;
    if (idx0 >= total) return;

    // Uniform per-thread setup (no smem, no __syncthreads): S is a warp-broadcast
    // L1-hit load; the two udivs are uniform and off the gather critical path.
    const int S = __ldg(image_size);
    const unsigned SS = (unsigned)S * (unsigned)S;
    int N = (int)((unsigned)zbuf_total / SS);
    if (N < 1) N = 1;
    int HWK = total / N;
    if (HWK < 1) HWK = 1;

    const bool has2 = (idx0 + 1) < total;
    const float Kc = 1000.0f * 1.4426950408889634f;

    // batch index per pixel: pow2 shift (common case) or udiv
    int b_[2];
    if ((HWK & (HWK - 1)) == 0) {
        const int sh = __ffs(HWK) - 1;
        b_[0] = idx0 >> sh;
        b_[1] = (idx0 + 1) >> sh;
    } else {
        b_[0] = idx0 / HWK;
        b_[1] = (idx0 + 1) / HWK;
    }

    int xs[2], ys[2];
    float C_[2];
    if (has2) {
        int4   cc = __ldg((const int4*)(xy + 2 * idx0));     // x0,y0,x1,y1
        float2 dd = __ldg((const float2*)(depth + idx0));
        xs[0] = cc.x; ys[0] = cc.y; xs[1] = cc.z; ys[1] = cc.w;
        C_[0] = (dd.x - 0.008f) * Kc;
        C_[1] = (dd.y - 0.008f) * Kc;
    } else {
        int2 cc = __ldg((const int2*)(xy + 2 * idx0));
        xs[0] = cc.x; ys[0] = cc.y; xs[1] = 0; ys[1] = 0;
        C_[0] = (__ldg(depth + idx0) - 0.008f) * Kc;
        C_[1] = 0.0f;
    }

    float acc[2] = {0.0f, 0.0f};

    if (((S & 3) == 0) && has2) {
        // ---- fast path: rows 16B-aligned ----
        const float* rows[2][3];
        bool d2_[2], d1_[2], lo_[2], hi_[2], nq_[2];

#pragma unroll
        for (int p = 0; p < 2; ++p) {
            const int x = xs[p], y = ys[p];
            const int ym = max(y - 1, 0);
            const int yp = min(y + 1, S - 1);
            const int xi = min(max(x, 1), S - 2);
            const int c0 = xi - 1;
            const int e16 = c0 & ~3;
            const int d   = c0 - e16;          // 0..3
            nq_[p] = (d >= 2);
            d2_[p] = (d & 2) != 0;
            d1_[p] = (d & 1) != 0;
            lo_[p] = (x < 1);
            hi_[p] = (x > S - 2);
            const float* zb = zbuf + (size_t)b_[p] * (size_t)SS;
            rows[p][0] = zb + (size_t)(unsigned)ym * (unsigned)S + e16;
            rows[p][1] = zb + (size_t)(unsigned)y  * (unsigned)S + e16;
            rows[p][2] = zb + (size_t)(unsigned)yp * (unsigned)S + e16;
        }

        // Issue all gathers before any consumption (max MLP).
        float4 P[2][3];
        float2 Q[2][3];
#pragma unroll
        for (int p = 0; p < 2; ++p)
#pragma unroll
            for (int r = 0; r < 3; ++r)
                P[p][r] = __ldg((const float4*)rows[p][r]);
#pragma unroll
        for (int p = 0; p < 2; ++p)
#pragma unroll
            for (int r = 0; r < 3; ++r) {
                Q[p][r] = make_float2(0.0f, 0.0f);
                if (nq_[p]) Q[p][r] = __ldg((const float2*)(rows[p][r] + 4));
            }

#pragma unroll
        for (int p = 0; p < 2; ++p) {
            const bool d2 = d2_[p], d1 = d1_[p], lo = lo_[p], hi = hi_[p];
            const float C = C_[p];
            float pv[9];
#pragma unroll
            for (int r = 0; r < 3; ++r) {
                float g0 = d2 ? P[p][r].z : P[p][r].x;
                float g1 = d2 ? P[p][r].w : P[p][r].y;
                float g2 = d2 ? Q[p][r].x : P[p][r].z;
                float g3 = d2 ? Q[p][r].y : P[p][r].w;
                float t0 = d1 ? g1 : g0;
                float t1 = d1 ? g2 : g1;
                float t2 = d1 ? g3 : g2;
                float vl = hi ? t1 : t0;
                float vm = lo ? t0 : (hi ? t2 : t1);
                float vr = lo ? t1 : t2;
                pv[3 * r + 0] = pval(vl, C, Kc);
                pv[3 * r + 1] = pval(vm, C, Kc);
                pv[3 * r + 2] = pval(vr, C, Kc);
            }
            acc[p] = quad_sum(pv[0], pv[1], pv[2], pv[3])
                   + quad_sum(pv[4], pv[5], pv[6], pv[7])
                   + rcpf(pv[8]);
        }

        float2 o = make_float2(acc[0] * (1.0f / 9.0f), acc[1] * (1.0f / 9.0f));
        *(float2*)(out + idx0) = o;
    } else {
        // ---- generic path: scalar gathers, rolled ----
        for (int p = 0; p < 2; ++p) {
            const int idx = idx0 + p;
            if (p == 1 && !has2) break;
            const int x = xs[p], y = ys[p];
            const int xm = max(x - 1, 0), xp = min(x + 1, S - 1);
            const int ym = max(y - 1, 0), yp = min(y + 1, S - 1);
            const float* zb = zbuf + (size_t)b_[p] * (size_t)SS;
            const float C = C_[p];
            float a = 0.0f;
            int yy[3] = {ym, y, yp};
            for (int r = 0; r < 3; ++r) {
                const float* rr = zb + (size_t)(unsigned)yy[r] * (unsigned)S;
                a += rcpf(pval(__ldg(rr + xm), C, Kc));
                a += rcpf(pval(__ldg(rr + x ), C, Kc));
                a += rcpf(pval(__ldg(rr + xp), C, Kc));
            }
            out[idx] = a * (1.0f / 9.0f);
        }
    }
}

extern "C" void kernel_launch(void* const* d_in, const int* in_sizes, int n_in,
                              void* d_out, int out_size) {
    const float* zbuf   = (const float*)d_in[0];
    const float* depth  = (const float*)d_in[1];
    const int*   xy     = (const int*)  d_in[2];
    const int*   imsz   = (const int*)  d_in[3];
    float*       out    = (float*)d_out;

    const int total      = in_sizes[1];
    const int zbuf_total = in_sizes[0];

    const int threads = 128;
    const int pairs   = (total + 1) / 2;
    const int blocks  = (pairs + threads - 1) / threads;
    shadow_pcf2_kernel<<<blocks, threads>>>(zbuf, depth, xy, imsz, out,
                                            total, zbuf_total);
}

// round 13
// speedup vs baseline: 1.2145x; 1.0344x over previous
#include <cuda_runtime.h>
#include <cuda_bf16.h>

// 3x3 PCF shadow visibility, 2 pixels per thread, 128-thread blocks.
// Window fetch = two aligned float2 loads per row (provably in-bounds for even S,
// same unique-sector cost as float4+predicated, fewer regs/selects).
// vis = (1/9) * sum sigmoid((zbuf[b, clamp(y+ii), clamp(x+jj)] - (z - 0.008)) * 1000)

__device__ __forceinline__ float ex2f(float x) {
    float y; asm("ex2.approx.f32 %0, %1;" : "=f"(y) : "f"(x)); return y;
}
__device__ __forceinline__ float rcpf(float x) {
    float y; asm("rcp.approx.f32 %0, %1;" : "=f"(y) : "f"(x)); return y;
}
__device__ __forceinline__ float quad_sum(float p0, float p1, float p2, float p3) {
    float a = p0 * p1, b = p2 * p3;
    return ((p0 + p1) * b + (p2 + p3) * a) * rcpf(a * b);
}
__device__ __forceinline__ float pval(float v, float C, float K) {
    float u = fmaf(-v, K, C);
    u = fminf(u, 30.0f);
    return 1.0f + ex2f(u);
}

__global__ __launch_bounds__(128) void shadow_pcf2_kernel(
    const float* __restrict__ zbuf,       // [N, S, S]
    const float* __restrict__ depth,      // [N, H, W, K]
    const int*   __restrict__ xy,         // [N, H, W, K, 2]
    const int*   __restrict__ image_size, // scalar S (device)
    float*       __restrict__ out,        // [N, H, W, K]
    int total,                            // N*H*W*K
    int zbuf_total)                       // N*S*S
{
    const int i    = blockIdx.x * blockDim.x + threadIdx.x;
    const int idx0 = 2 * i;
    if (idx0 >= total) return;

    // Uniform per-thread setup (no smem, no __syncthreads).
    const int S = __ldg(image_size);
    const unsigned SS = (unsigned)S * (unsigned)S;
    int N = (int)((unsigned)zbuf_total / SS);
    if (N < 1) N = 1;
    int HWK = total / N;
    if (HWK < 1) HWK = 1;

    const bool has2 = (idx0 + 1) < total;
    const float Kc = 1000.0f * 1.4426950408889634f;

    // batch index per pixel: pow2 shift (common case) or udiv
    int b_[2];
    if ((HWK & (HWK - 1)) == 0) {
        const int sh = __ffs(HWK) - 1;
        b_[0] = idx0 >> sh;
        b_[1] = (idx0 + 1) >> sh;
    } else {
        b_[0] = idx0 / HWK;
        b_[1] = (idx0 + 1) / HWK;
    }

    int xs[2], ys[2];
    float C_[2];
    if (has2) {
        int4   cc = __ldg((const int4*)(xy + 2 * idx0));     // x0,y0,x1,y1
        float2 dd = __ldg((const float2*)(depth + idx0));
        xs[0] = cc.x; ys[0] = cc.y; xs[1] = cc.z; ys[1] = cc.w;
        C_[0] = (dd.x - 0.008f) * Kc;
        C_[1] = (dd.y - 0.008f) * Kc;
    } else {
        int2 cc = __ldg((const int2*)(xy + 2 * idx0));
        xs[0] = cc.x; ys[0] = cc.y; xs[1] = 0; ys[1] = 0;
        C_[0] = (__ldg(depth + idx0) - 0.008f) * Kc;
        C_[1] = 0.0f;
    }

    float acc[2] = {0.0f, 0.0f};

    if (((S & 1) == 0) && has2) {
        // ---- fast path (even S, rows 8B-aligned) ----
        // Interior-clamp column: taps are [c0, c0+2]; fetch floats [e8, e8+3]
        // via two aligned float2 loads. Bounds: c0 in [0, S-3]; c0 even -> c0 <= S-4
        // (S even), c0 odd -> e8 = c0-1 <= S-4. So e8+3 <= S-1 always.
        const float* rows[2][3];
        bool d1_[2], lo_[2], hi_[2];

#pragma unroll
        for (int p = 0; p < 2; ++p) {
            const int x = xs[p], y = ys[p];
            const int ym = max(y - 1, 0);
            const int yp = min(y + 1, S - 1);
            const int xi = min(max(x, 1), S - 2);
            const int c0 = xi - 1;                // in [0, S-3]
            const int e8 = c0 & ~1;
            d1_[p] = (c0 & 1) != 0;
            lo_[p] = (x < 1);
            hi_[p] = (x > S - 2);
            const float* zb = zbuf + (size_t)b_[p] * (size_t)SS;
            rows[p][0] = zb + (size_t)(unsigned)ym * (unsigned)S + e8;
            rows[p][1] = zb + (size_t)(unsigned)y  * (unsigned)S + e8;
            rows[p][2] = zb + (size_t)(unsigned)yp * (unsigned)S + e8;
        }

        // Issue all 12 gathers before any consumption (max MLP).
        float2 A[2][3], B[2][3];
#pragma unroll
        for (int p = 0; p < 2; ++p)
#pragma unroll
            for (int r = 0; r < 3; ++r) {
                A[p][r] = __ldg((const float2*)rows[p][r]);
                B[p][r] = __ldg((const float2*)(rows[p][r] + 2));
            }

#pragma unroll
        for (int p = 0; p < 2; ++p) {
            const bool d1 = d1_[p], lo = lo_[p], hi = hi_[p];
            const float C = C_[p];
            float pv[9];
#pragma unroll
            for (int r = 0; r < 3; ++r) {
                // window values at [c0, c0+2]
                float t0 = d1 ? A[p][r].y : A[p][r].x;
                float t1 = d1 ? B[p][r].x : A[p][r].y;
                float t2 = d1 ? B[p][r].y : B[p][r].x;
                // remap for x==0 / x==S-1 edge clamping
                float vl = hi ? t1 : t0;
                float vm = lo ? t0 : (hi ? t2 : t1);
                float vr = lo ? t1 : t2;
                pv[3 * r + 0] = pval(vl, C, Kc);
                pv[3 * r + 1] = pval(vm, C, Kc);
                pv[3 * r + 2] = pval(vr, C, Kc);
            }
            acc[p] = quad_sum(pv[0], pv[1], pv[2], pv[3])
                   + quad_sum(pv[4], pv[5], pv[6], pv[7])
                   + rcpf(pv[8]);
        }

        float2 o = make_float2(acc[0] * (1.0f / 9.0f), acc[1] * (1.0f / 9.0f));
        *(float2*)(out + idx0) = o;
    } else {
        // ---- generic path (odd S or tail): scalar gathers, rolled ----
        for (int p = 0; p < 2; ++p) {
            const int idx = idx0 + p;
            if (p == 1 && !has2) break;
            const int x = xs[p], y = ys[p];
            const int xm = max(x - 1, 0), xp = min(x + 1, S - 1);
            const int ym = max(y - 1, 0), yp = min(y + 1, S - 1);
            const float* zb = zbuf + (size_t)b_[p] * (size_t)SS;
            const float C = C_[p];
            float a = 0.0f;
            int yy[3] = {ym, y, yp};
            for (int r = 0; r < 3; ++r) {
                const float* rr = zb + (size_t)(unsigned)yy[r] * (unsigned)S;
                a += rcpf(pval(__ldg(rr + xm), C, Kc));
                a += rcpf(pval(__ldg(rr + x ), C, Kc));
                a += rcpf(pval(__ldg(rr + xp), C, Kc));
            }
            out[idx] = a * (1.0f / 9.0f);
        }
    }
}

extern "C" void kernel_launch(void* const* d_in, const int* in_sizes, int n_in,
                              void* d_out, int out_size) {
    const float* zbuf   = (const float*)d_in[0];
    const float* depth  = (const float*)d_in[1];
    const int*   xy     = (const int*)  d_in[2];
    const int*   imsz   = (const int*)  d_in[3];
    float*       out    = (float*)d_out;

    const int total      = in_sizes[1];
    const int zbuf_total = in_sizes[0];

    const int threads = 128;
    const int pairs   = (total + 1) / 2;
    const int blocks  = (pairs + threads - 1) / threads;
    shadow_pcf2_kernel<<<blocks, threads>>>(zbuf, depth, xy, imsz, out,
                                            total, zbuf_total);
}

// round 14
// speedup vs baseline: 1.2496x; 1.0289x over previous
#include <cuda_runtime.h>
#include <cuda_bf16.h>

// 3x3 PCF shadow visibility, 2 pixels per thread, 128-thread blocks.
// Window fetch = two aligned float2 loads per row; gather addresses carried as
// 32-bit element offsets (not 64-bit pointers) to cut live registers.
// vis = (1/9) * sum sigmoid((zbuf[b, clamp(y+ii), clamp(x+jj)] - (z - 0.008)) * 1000)

__device__ __forceinline__ float ex2f(float x) {
    float y; asm("ex2.approx.f32 %0, %1;" : "=f"(y) : "f"(x)); return y;
}
__device__ __forceinline__ float rcpf(float x) {
    float y; asm("rcp.approx.f32 %0, %1;" : "=f"(y) : "f"(x)); return y;
}
__device__ __forceinline__ float quad_sum(float p0, float p1, float p2, float p3) {
    float a = p0 * p1, b = p2 * p3;
    return ((p0 + p1) * b + (p2 + p3) * a) * rcpf(a * b);
}
__device__ __forceinline__ float pval(float v, float C, float K) {
    float u = fmaf(-v, K, C);
    u = fminf(u, 30.0f);
    return 1.0f + ex2f(u);
}

__global__ __launch_bounds__(128) void shadow_pcf2_kernel(
    const float* __restrict__ zbuf,       // [N, S, S]
    const float* __restrict__ depth,      // [N, H, W, K]
    const int*   __restrict__ xy,         // [N, H, W, K, 2]
    const int*   __restrict__ image_size, // scalar S (device)
    float*       __restrict__ out,        // [N, H, W, K]
    int total,                            // N*H*W*K
    int zbuf_total)                       // N*S*S
{
    const int i    = blockIdx.x * blockDim.x + threadIdx.x;
    const int idx0 = 2 * i;
    if (idx0 >= total) return;

    // Uniform per-thread setup (no smem, no __syncthreads).
    const int S = __ldg(image_size);
    const unsigned SS = (unsigned)S * (unsigned)S;
    int N = (int)((unsigned)zbuf_total / SS);
    if (N < 1) N = 1;
    int HWK = total / N;
    if (HWK < 1) HWK = 1;

    const bool has2 = (idx0 + 1) < total;
    const float Kc = 1000.0f * 1.4426950408889634f;

    // batch index per pixel: pow2 shift (common case) or udiv
    int b_[2];
    if ((HWK & (HWK - 1)) == 0) {
        const int sh = __ffs(HWK) - 1;
        b_[0] = idx0 >> sh;
        b_[1] = (idx0 + 1) >> sh;
    } else {
        b_[0] = idx0 / HWK;
        b_[1] = (idx0 + 1) / HWK;
    }

    int xs[2], ys[2];
    float C_[2];
    if (has2) {
        int4   cc = __ldg((const int4*)(xy + 2 * idx0));     // x0,y0,x1,y1
        float2 dd = __ldg((const float2*)(depth + idx0));
        xs[0] = cc.x; ys[0] = cc.y; xs[1] = cc.z; ys[1] = cc.w;
        C_[0] = (dd.x - 0.008f) * Kc;
        C_[1] = (dd.y - 0.008f) * Kc;
    } else {
        int2 cc = __ldg((const int2*)(xy + 2 * idx0));
        xs[0] = cc.x; ys[0] = cc.y; xs[1] = 0; ys[1] = 0;
        C_[0] = (__ldg(depth + idx0) - 0.008f) * Kc;
        C_[1] = 0.0f;
    }

    float acc[2] = {0.0f, 0.0f};

    if (((S & 1) == 0) && has2) {
        // ---- fast path (even S, rows 8B-aligned) ----
        // Taps are [c0, c0+2]; fetch floats [e8, e8+3] via two aligned float2
        // loads. Bounds: c0 in [0,S-3]; e8 = c0&~1 <= S-4 for even S, so
        // e8+3 <= S-1 always. Offsets kept as 32-bit element indices.
        unsigned off[2][3];
        bool d1_[2], lo_[2], hi_[2];

#pragma unroll
        for (int p = 0; p < 2; ++p) {
            const int x = xs[p], y = ys[p];
            const int ym = max(y - 1, 0);
            const int yp = min(y + 1, S - 1);
            const int xi = min(max(x, 1), S - 2);
            const int c0 = xi - 1;                // in [0, S-3]
            const int e8 = c0 & ~1;
            d1_[p] = (c0 & 1) != 0;
            lo_[p] = (x < 1);
            hi_[p] = (x > S - 2);
            const unsigned bb = (unsigned)b_[p] * SS + (unsigned)e8;
            off[p][0] = bb + (unsigned)ym * (unsigned)S;
            off[p][1] = bb + (unsigned)y  * (unsigned)S;
            off[p][2] = bb + (unsigned)yp * (unsigned)S;
        }

        // Issue all 12 gathers before any consumption (max MLP).
        float2 A[2][3], B[2][3];
#pragma unroll
        for (int p = 0; p < 2; ++p)
#pragma unroll
            for (int r = 0; r < 3; ++r) {
                A[p][r] = __ldg((const float2*)(zbuf + off[p][r]));
                B[p][r] = __ldg((const float2*)(zbuf + off[p][r] + 2));
            }

#pragma unroll
        for (int p = 0; p < 2; ++p) {
            const bool d1 = d1_[p], lo = lo_[p], hi = hi_[p];
            const float C = C_[p];
            float pv[9];
#pragma unroll
            for (int r = 0; r < 3; ++r) {
                // window values at [c0, c0+2]
                float t0 = d1 ? A[p][r].y : A[p][r].x;
                float t1 = d1 ? B[p][r].x : A[p][r].y;
                float t2 = d1 ? B[p][r].y : B[p][r].x;
                // remap for x==0 / x==S-1 edge clamping
                float vl = hi ? t1 : t0;
                float vm = lo ? t0 : (hi ? t2 : t1);
                float vr = lo ? t1 : t2;
                pv[3 * r + 0] = pval(vl, C, Kc);
                pv[3 * r + 1] = pval(vm, C, Kc);
                pv[3 * r + 2] = pval(vr, C, Kc);
            }
            acc[p] = quad_sum(pv[0], pv[1], pv[2], pv[3])
                   + quad_sum(pv[4], pv[5], pv[6], pv[7])
                   + rcpf(pv[8]);
        }

        float2 o = make_float2(acc[0] * (1.0f / 9.0f), acc[1] * (1.0f / 9.0f));
        *(float2*)(out + idx0) = o;
    } else {
        // ---- generic path (odd S or tail): scalar gathers, rolled ----
        for (int p = 0; p < 2; ++p) {
            const int idx = idx0 + p;
            if (p == 1 && !has2) break;
            const int x = xs[p], y = ys[p];
            const int xm = max(x - 1, 0), xp = min(x + 1, S - 1);
            const int ym = max(y - 1, 0), yp = min(y + 1, S - 1);
            const float* zb = zbuf + (size_t)b_[p] * (size_t)SS;
            const float C = C_[p];
            float a = 0.0f;
            int yy[3] = {ym, y, yp};
            for (int r = 0; r < 3; ++r) {
                const float* rr = zb + (size_t)(unsigned)yy[r] * (unsigned)S;
                a += rcpf(pval(__ldg(rr + xm), C, Kc));
                a += rcpf(pval(__ldg(rr + x ), C, Kc));
                a += rcpf(pval(__ldg(rr + xp), C, Kc));
            }
            out[idx] = a * (1.0f / 9.0f);
        }
    }
}

extern "C" void kernel_launch(void* const* d_in, const int* in_sizes, int n_in,
                              void* d_out, int out_size) {
    const float* zbuf   = (const float*)d_in[0];
    const float* depth  = (const float*)d_in[1];
    const int*   xy     = (const int*)  d_in[2];
    const int*   imsz   = (const int*)  d_in[3];
    float*       out    = (float*)d_out;

    const int total      = in_sizes[1];
    const int zbuf_total = in_sizes[0];

    const int threads = 128;
    const int pairs   = (total + 1) / 2;
    const int blocks  = (pairs + threads - 1) / threads;
    shadow_pcf2_kernel<<<blocks, threads>>>(zbuf, depth, xy, imsz, out,
                                            total, zbuf_total);
}